// round 11
// baseline (speedup 1.0000x reference)
#include <cuda_runtime.h>
#include <cuda_fp16.h>
#include <cstdint>
#include <math.h>

#define NB 16
#define NA 2048
#define ND 512
#define NR 10
#define INV_SQRT_DK 0.04419417382415922f  // 1/sqrt(512)

// Scratch (no device allocations allowed)
__device__ float  g_left[(size_t)NB * NA * NR];    // left proj, pre-scaled by 1/sqrt(dk)
__device__ float  g_rightT[(size_t)NB * NA * NR];  // right proj, [b][c][r]
__device__ __half g_xh[(size_t)NB * NA * ND];      // x pre-converted to half
__device__ __half g_p[(size_t)NB * NA * NA];       // unnormalized attn weights exp(s), fp16
__device__ float  g_psum[(size_t)NB * NA];         // per-row softmax denominators

__device__ __forceinline__ uint32_t smem_u32(const void* p) {
    uint32_t a;
    asm("{ .reg .u64 t; cvta.to.shared.u64 t, %1; cvt.u32.u64 %0, t; }" : "=r"(a) : "l"(p));
    return a;
}
__device__ __forceinline__ void cp_async16(uint32_t saddr, const void* gptr) {
    asm volatile("cp.async.cg.shared.global [%0], [%1], 16;" :: "r"(saddr), "l"(gptr) : "memory");
}
#define CP_COMMIT() asm volatile("cp.async.commit_group;" ::: "memory")
#define CP_WAIT1()  asm volatile("cp.async.wait_group 1;" ::: "memory")

__device__ __forceinline__ void mma_f16(float* d, const uint32_t* a, const uint32_t* bfr) {
    asm volatile(
        "mma.sync.aligned.m16n8k16.row.col.f32.f16.f16.f32 "
        "{%0,%1,%2,%3}, {%4,%5,%6,%7}, {%8,%9}, {%0,%1,%2,%3};"
        : "+f"(d[0]), "+f"(d[1]), "+f"(d[2]), "+f"(d[3])
        : "r"(a[0]), "r"(a[1]), "r"(a[2]), "r"(a[3]), "r"(bfr[0]), "r"(bfr[1]));
}
__device__ __forceinline__ void ldsm_x4(uint32_t* r, uint32_t saddr) {
    asm volatile("ldmatrix.sync.aligned.m8n8.x4.shared.b16 {%0,%1,%2,%3}, [%4];"
                 : "=r"(r[0]), "=r"(r[1]), "=r"(r[2]), "=r"(r[3]) : "r"(saddr));
}
__device__ __forceinline__ void ldsm_x4_t(uint32_t* r, uint32_t saddr) {
    asm volatile("ldmatrix.sync.aligned.m8n8.x4.trans.shared.b16 {%0,%1,%2,%3}, [%4];"
                 : "=r"(r[0]), "=r"(r[1]), "=r"(r[2]), "=r"(r[3]) : "r"(saddr));
}
__device__ __forceinline__ uint32_t pack_h2(float lo, float hi) {
    uint32_t u;
    asm("cvt.rn.f16x2.f32 %0, %1, %2;" : "=r"(u) : "f"(hi), "f"(lo));  // lo -> .x
    return u;
}

// ===========================================================================
// K1: projections + x->half conversion. 2 rows/warp for low regs -> 4 CTAs/SM.
// ===========================================================================
__global__ void __launch_bounds__(256)
k1_proj(const float* __restrict__ x, const float* __restrict__ W1,
        const float* __restrict__ W2) {
    __shared__ float W1T[NR][ND];
    __shared__ float W2s[NR][ND];
    int tid = threadIdx.x;
    for (int idx = tid; idx < ND * NR; idx += 256) {
        int d = idx / NR, r = idx % NR;
        W1T[r][d] = W1[idx];               // W1 [D, R], r fastest
    }
    for (int idx = tid; idx < NR * ND; idx += 256) {
        W2s[idx / ND][idx % ND] = W2[idx]; // W2 [R, D], d fastest
    }
    __syncthreads();

    int warp = tid >> 5, lane = tid & 31;
    int row0 = blockIdx.x * 16 + warp * 2;   // 2 rows per warp
    const float* xr0 = x + (size_t)row0 * ND;
    __half* xh0 = g_xh + (size_t)row0 * ND;

    float accL[2][NR], accR[2][NR];
#pragma unroll
    for (int i = 0; i < 2; i++)
#pragma unroll
        for (int r = 0; r < NR; r++) { accL[i][r] = 0.f; accR[i][r] = 0.f; }

#pragma unroll 4
    for (int k = 0; k < ND / 32; k++) {
        int d = lane + 32 * k;
        float xv0 = xr0[d];
        float xv1 = xr0[ND + d];
        xh0[d]      = __float2half_rn(xv0);
        xh0[ND + d] = __float2half_rn(xv1);
#pragma unroll
        for (int r = 0; r < NR; r++) {
            float w1 = W1T[r][d];
            float w2 = W2s[r][d];
            accL[0][r] += xv0 * w1;
            accL[1][r] += xv1 * w1;
            accR[0][r] += xv0 * w2;
            accR[1][r] += xv1 * w2;
        }
    }
#pragma unroll
    for (int i = 0; i < 2; i++)
#pragma unroll
        for (int r = 0; r < NR; r++) {
#pragma unroll
            for (int off = 16; off; off >>= 1) {
                accL[i][r] += __shfl_down_sync(0xffffffffu, accL[i][r], off);
                accR[i][r] += __shfl_down_sync(0xffffffffu, accR[i][r], off);
            }
        }
    if (lane == 0) {
#pragma unroll
        for (int i = 0; i < 2; i++) {
            float* lp = g_left   + (size_t)(row0 + i) * NR;
            float* rp = g_rightT + (size_t)(row0 + i) * NR;
#pragma unroll
            for (int r = 0; r < NR; r++) {
                lp[r] = accL[i][r] * INV_SQRT_DK;
                rp[r] = accR[i][r];
            }
        }
    }
}

// ===========================================================================
// K2: P'[b][a][c] = exp(left_a . right_c) (fp16) + row sums (f32).
//   CTA: 64 rows x 2048 keys, 256 threads = 16 mg x 16 kg.
//   rightT staged once per batch block, swizzled for conflict-free LDS.
// ===========================================================================
#define K2_SMEM ((NA * NR + NA / 16 + 32) * 4)

__global__ void __launch_bounds__(256, 2)
k2_pgen() {
    extern __shared__ float rt[];
    int tid = threadIdx.x;
    int b  = blockIdx.y;
    int a0 = blockIdx.x * 64;

    {
        const float* src = g_rightT + (size_t)b * NA * NR;
        for (int g = tid; g < NA * NR; g += 256)
            rt[g + g / 160] = src[g];
    }

    int mg = tid >> 4;     // 0..15
    int kg = tid & 15;     // 0..15

    float ls[4][NR];
#pragma unroll
    for (int i = 0; i < 4; i++) {
        const float* lp = g_left + ((size_t)b * NA + a0 + mg + 16 * i) * NR;
#pragma unroll
        for (int r = 0; r < NR; r++) ls[i][r] = lp[r];
    }
    float lacc[4] = {0.f, 0.f, 0.f, 0.f};

    __syncthreads();

    __half* pb = g_p + ((size_t)b * NA) * NA;

#pragma unroll 1
    for (int stripe = 0; stripe < 16; stripe++) {
        int cbase = stripe * 128 + kg * 8;
        float e[4][8];
#pragma unroll
        for (int j = 0; j < 8; j++) {
            int c = cbase + j;
            const float* rp = rt + c * NR + (c >> 4);
            float rv[NR];
#pragma unroll
            for (int r = 0; r < NR; r++) rv[r] = rp[r];
#pragma unroll
            for (int i = 0; i < 4; i++) {
                float s = 0.f;
#pragma unroll
                for (int r = 0; r < NR; r++) s += ls[i][r] * rv[r];
                float ev = __expf(s);
                e[i][j] = ev;
                lacc[i] += ev;
            }
        }
#pragma unroll
        for (int i = 0; i < 4; i++) {
            uint4 t;
            t.x = pack_h2(e[i][0], e[i][1]);
            t.y = pack_h2(e[i][2], e[i][3]);
            t.z = pack_h2(e[i][4], e[i][5]);
            t.w = pack_h2(e[i][6], e[i][7]);
            *(uint4*)(pb + (size_t)(a0 + mg + 16 * i) * NA + cbase) = t;
        }
    }

#pragma unroll
    for (int off = 1; off < 16; off <<= 1)
#pragma unroll
        for (int i = 0; i < 4; i++)
            lacc[i] += __shfl_xor_sync(0xffffffffu, lacc[i], off);
    if (kg == 0) {
#pragma unroll
        for (int i = 0; i < 4; i++)
            g_psum[(size_t)b * NA + a0 + mg + 16 * i] = lacc[i];
    }
}

// ===========================================================================
// K3: pure fp16 GEMM out = (P' @ xh) / psum.
//   CTA: M=128 x N=128, 256 threads (8 warps = 2m x 4n, warp tile 64x32),
//   2 CTAs/SM. KC=64 (4 k16 steps), 32 chunks.
//   Triple-buffered cp.async (A+B), prefetch distance 2 after the barrier,
//   wait_group 1 keeps one chunk in flight. One barrier per chunk.
//   A stride 72h=144B, B stride 136h=272B: conflict-free ldmatrix phases.
// ===========================================================================
#define KC 64
#define NCHUNK (NA / KC)          // 32
#define AH_STRIDE 72              // halves
#define AH_BUF (128 * AH_STRIDE)  // 9216 halves per buffer
#define BH_STRIDE 136             // halves
#define BH_BUF (KC * BH_STRIDE)   // 8704 halves per buffer
// dynamic smem (bytes)
#define OFF_A 0                   // 3*9216*2 = 55296
#define OFF_B 55296               // 3*8704*2 = 52224
#define OFF_SL 107520             // 128*4 = 512
#define SMEM_K3 108032

__global__ void __launch_bounds__(256, 2)
k3_gemm(float* __restrict__ out) {
    extern __shared__ char smem[];
    float* sl = (float*)(smem + OFF_SL);
    uint32_t sb = smem_u32(smem);

    int tid = threadIdx.x;
    int wid = tid >> 5, lane = tid & 31;
    int b  = blockIdx.z;
    int a0 = blockIdx.x * 128;
    int n0 = blockIdx.y * 128;

    int wm = wid >> 2, wn = wid & 3;   // 2m x 4n, warp tile 64x32
    int fs = lane & 3, fq = lane >> 2;

    float acc[4][4][4];
#pragma unroll
    for (int mt = 0; mt < 4; mt++)
#pragma unroll
        for (int nt = 0; nt < 4; nt++)
#pragma unroll
            for (int q = 0; q < 4; q++) acc[mt][nt][q] = 0.f;

    const __half* pA = g_p  + ((size_t)b * NA + a0) * NA;   // rows stride NA
    const __half* pB = g_xh + (size_t)b * NA * ND;

    // prefetch A+B for one chunk into buffer pb
#define PREFETCH(chunk, pb)                                                     \
    do {                                                                        \
        _Pragma("unroll")                                                       \
        for (int it = 0; it < 4; it++) {                                        \
            int u = tid + 256 * it;          /* 1024 units: A 128r x 8seg */    \
            int row = u >> 3, seg = u & 7;                                      \
            uint32_t dst = sb + OFF_A +                                         \
                (uint32_t)((pb) * AH_BUF + row * AH_STRIDE + seg * 8) * 2;      \
            cp_async16(dst, pA + (size_t)row * NA + (chunk) * KC + seg * 8);    \
        }                                                                       \
        _Pragma("unroll")                                                       \
        for (int it = 0; it < 4; it++) {                                        \
            int u = tid + 256 * it;          /* 1024 units: B 64r x 16seg */    \
            int row = u >> 4, seg = u & 15;                                     \
            uint32_t dst = sb + OFF_B +                                         \
                (uint32_t)((pb) * BH_BUF + row * BH_STRIDE + seg * 8) * 2;      \
            cp_async16(dst, pB + (size_t)((chunk) * KC + row) * ND + n0 + seg * 8); \
        }                                                                       \
    } while (0)

    // prologue: row sums + two chunks in flight
    if (tid < 128) sl[tid] = g_psum[(size_t)b * NA + a0 + tid];
    PREFETCH(0, 0); CP_COMMIT();
    PREFETCH(1, 1); CP_COMMIT();

    for (int c = 0; c < NCHUNK; c++) {
        int buf = c % 3;

        CP_WAIT1();        // chunk c landed (c+1 may be in flight)
        __syncthreads();   // visible to all; buffer (c+2)%3 free (MMA c-1 done)

        if (c + 2 < NCHUNK) PREFETCH(c + 2, (c + 2) % 3);
        CP_COMMIT();       // unconditional: keeps wait_group accounting fixed

        uint32_t abase = sb + OFF_A + (uint32_t)(buf * AH_BUF) * 2;
        uint32_t bbase = sb + OFF_B + (uint32_t)(buf * BH_BUF) * 2;
#pragma unroll
        for (int ks = 0; ks < 4; ks++) {
            uint32_t afr[4][4], bfr[4][2];
            {
                int arow = wm * 64 + (lane & 15);
                int acol = ks * 16 + (lane >> 4) * 8;
                uint32_t base = abase + (uint32_t)(arow * AH_STRIDE + acol) * 2;
#pragma unroll
                for (int mt = 0; mt < 4; mt++)
                    ldsm_x4(afr[mt], base + (uint32_t)(mt * 16 * AH_STRIDE) * 2);
            }
            {
                int brow = ks * 16 + (lane & 15);
                int bcol = wn * 32 + (lane >> 4) * 8;
                uint32_t base = bbase + (uint32_t)(brow * BH_STRIDE + bcol) * 2;
#pragma unroll
                for (int np = 0; np < 2; np++) {
                    uint32_t q[4];
                    ldsm_x4_t(q, base + (uint32_t)(np * 16) * 2);
                    bfr[2 * np][0]     = q[0]; bfr[2 * np][1]     = q[1];
                    bfr[2 * np + 1][0] = q[2]; bfr[2 * np + 1][1] = q[3];
                }
            }
#pragma unroll
            for (int mt = 0; mt < 4; mt++)
#pragma unroll
                for (int nt = 0; nt < 4; nt++)
                    mma_f16(acc[mt][nt], afr[mt], bfr[nt]);
        }
    }

    // epilogue: normalize + store
#pragma unroll
    for (int mt = 0; mt < 4; mt++) {
        int r0 = wm * 64 + mt * 16 + fq;
        int r1 = r0 + 8;
        float inv0 = 1.0f / sl[r0];
        float inv1 = 1.0f / sl[r1];
        float* op0 = out + ((size_t)b * NA + a0 + r0) * ND + n0;
        float* op1 = out + ((size_t)b * NA + a0 + r1) * ND + n0;
#pragma unroll
        for (int nt = 0; nt < 4; nt++) {
            int col = wn * 32 + nt * 8 + 2 * fs;
            float2 v0 = make_float2(acc[mt][nt][0] * inv0, acc[mt][nt][1] * inv0);
            float2 v1 = make_float2(acc[mt][nt][2] * inv1, acc[mt][nt][3] * inv1);
            *(float2*)&op0[col] = v0;
            *(float2*)&op1[col] = v1;
        }
    }
}

// ---------------------------------------------------------------------------
extern "C" void kernel_launch(void* const* d_in, const int* in_sizes, int n_in,
                              void* d_out, int out_size) {
    const float* x  = (const float*)d_in[0];
    const float* W1 = (const float*)d_in[1];
    const float* W2 = (const float*)d_in[2];
    float* out = (float*)d_out;

    static bool attr_set = false;
    if (!attr_set) {
        cudaFuncSetAttribute(k2_pgen, cudaFuncAttributeMaxDynamicSharedMemorySize, K2_SMEM);
        cudaFuncSetAttribute(k3_gemm, cudaFuncAttributeMaxDynamicSharedMemorySize, SMEM_K3);
        attr_set = true;
    }

    k1_proj<<<(NB * NA) / 16, 256>>>(x, W1, W2);
    k2_pgen<<<dim3(NA / 64, NB), 256, K2_SMEM>>>();
    k3_gemm<<<dim3(NA / 128, ND / 128, NB), 256, SMEM_K3>>>(out);
}

// round 12
// speedup vs baseline: 1.0334x; 1.0334x over previous
#include <cuda_runtime.h>
#include <cuda_fp16.h>
#include <cstdint>
#include <math.h>

#define NB 16
#define NA 2048
#define ND 512
#define NR 10
#define INV_SQRT_DK 0.04419417382415922f  // 1/sqrt(512)

// Scratch (no device allocations allowed)
__device__ float  g_left[(size_t)NB * NA * NR];    // left proj, pre-scaled by 1/sqrt(dk)
__device__ float  g_rightT[(size_t)NB * NA * NR];  // right proj, [b][c][r]
__device__ __half g_xh[(size_t)NB * NA * ND];      // x pre-converted to half
__device__ __half g_p[(size_t)NB * NA * NA];       // unnormalized attn weights exp(s), fp16
__device__ float  g_psum[(size_t)NB * NA];         // per-row softmax denominators

__device__ __forceinline__ uint32_t smem_u32(const void* p) {
    uint32_t a;
    asm("{ .reg .u64 t; cvta.to.shared.u64 t, %1; cvt.u32.u64 %0, t; }" : "=r"(a) : "l"(p));
    return a;
}
__device__ __forceinline__ void cp_async16(uint32_t saddr, const void* gptr) {
    asm volatile("cp.async.cg.shared.global [%0], [%1], 16;" :: "r"(saddr), "l"(gptr) : "memory");
}
#define CP_COMMIT() asm volatile("cp.async.commit_group;" ::: "memory")
#define CP_WAIT1()  asm volatile("cp.async.wait_group 1;" ::: "memory")

__device__ __forceinline__ void mma_f16(float* d, const uint32_t* a, const uint32_t* bfr) {
    asm volatile(
        "mma.sync.aligned.m16n8k16.row.col.f32.f16.f16.f32 "
        "{%0,%1,%2,%3}, {%4,%5,%6,%7}, {%8,%9}, {%0,%1,%2,%3};"
        : "+f"(d[0]), "+f"(d[1]), "+f"(d[2]), "+f"(d[3])
        : "r"(a[0]), "r"(a[1]), "r"(a[2]), "r"(a[3]), "r"(bfr[0]), "r"(bfr[1]));
}
__device__ __forceinline__ void ldsm_x4(uint32_t* r, uint32_t saddr) {
    asm volatile("ldmatrix.sync.aligned.m8n8.x4.shared.b16 {%0,%1,%2,%3}, [%4];"
                 : "=r"(r[0]), "=r"(r[1]), "=r"(r[2]), "=r"(r[3]) : "r"(saddr));
}
__device__ __forceinline__ void ldsm_x4_t(uint32_t* r, uint32_t saddr) {
    asm volatile("ldmatrix.sync.aligned.m8n8.x4.trans.shared.b16 {%0,%1,%2,%3}, [%4];"
                 : "=r"(r[0]), "=r"(r[1]), "=r"(r[2]), "=r"(r[3]) : "r"(saddr));
}
__device__ __forceinline__ uint32_t pack_h2(float lo, float hi) {
    uint32_t u;
    asm("cvt.rn.f16x2.f32 %0, %1, %2;" : "=r"(u) : "f"(hi), "f"(lo));  // lo -> .x
    return u;
}

// ===========================================================================
// K1: projections + x->half conversion. 4 rows/warp; float4 LDG/LDS/ST.
// ===========================================================================
__global__ void __launch_bounds__(256)
k1_proj(const float* __restrict__ x, const float* __restrict__ W1,
        const float* __restrict__ W2) {
    __shared__ float W1T[NR][ND];
    __shared__ float W2s[NR][ND];
    int tid = threadIdx.x;
    for (int idx = tid; idx < ND * NR; idx += 256) {
        int d = idx / NR, r = idx % NR;
        W1T[r][d] = W1[idx];               // W1 [D, R], r fastest
    }
    for (int idx = tid; idx < NR * ND; idx += 256) {
        W2s[idx / ND][idx % ND] = W2[idx]; // W2 [R, D], d fastest
    }
    __syncthreads();

    int warp = tid >> 5, lane = tid & 31;
    int row0 = blockIdx.x * 32 + warp * 4;
    const float4* xr4 = (const float4*)(x + (size_t)row0 * ND);  // row stride 128 f4
    __half* xh0 = g_xh + (size_t)row0 * ND;

    float accL[4][NR], accR[4][NR];
#pragma unroll
    for (int i = 0; i < 4; i++)
#pragma unroll
        for (int r = 0; r < NR; r++) { accL[i][r] = 0.f; accR[i][r] = 0.f; }

#pragma unroll
    for (int k = 0; k < 4; k++) {
        int q = lane + 32 * k;             // float4 index within row, 0..127
        float4 xv[4];
#pragma unroll
        for (int i = 0; i < 4; i++) xv[i] = xr4[(size_t)i * 128 + q];
#pragma unroll
        for (int i = 0; i < 4; i++) {
            uint2 h;
            h.x = pack_h2(xv[i].x, xv[i].y);
            h.y = pack_h2(xv[i].z, xv[i].w);
            *(uint2*)(xh0 + (size_t)i * ND + 4 * q) = h;
        }
#pragma unroll
        for (int r = 0; r < NR; r++) {
            float4 w1 = *(const float4*)&W1T[r][4 * q];
            float4 w2 = *(const float4*)&W2s[r][4 * q];
#pragma unroll
            for (int i = 0; i < 4; i++) {
                accL[i][r] += xv[i].x * w1.x + xv[i].y * w1.y
                            + xv[i].z * w1.z + xv[i].w * w1.w;
                accR[i][r] += xv[i].x * w2.x + xv[i].y * w2.y
                            + xv[i].z * w2.z + xv[i].w * w2.w;
            }
        }
    }
#pragma unroll
    for (int i = 0; i < 4; i++)
#pragma unroll
        for (int r = 0; r < NR; r++) {
#pragma unroll
            for (int off = 16; off; off >>= 1) {
                accL[i][r] += __shfl_down_sync(0xffffffffu, accL[i][r], off);
                accR[i][r] += __shfl_down_sync(0xffffffffu, accR[i][r], off);
            }
        }
    if (lane == 0) {
#pragma unroll
        for (int i = 0; i < 4; i++) {
            float* lp = g_left   + (size_t)(row0 + i) * NR;
            float* rp = g_rightT + (size_t)(row0 + i) * NR;
#pragma unroll
            for (int r = 0; r < NR; r++) {
                lp[r] = accL[i][r] * INV_SQRT_DK;
                rp[r] = accR[i][r];
            }
        }
    }
}

// ===========================================================================
// K2: P'[b][a][c] = exp(left_a . right_c) (fp16) + row sums (f32).
//   CTA: 64 rows x 2048 keys, 256 threads = 16 mg x 16 kg.
//   rightT staged once per batch block, swizzled for conflict-free LDS.
// ===========================================================================
#define K2_SMEM ((NA * NR + NA / 16 + 32) * 4)

__global__ void __launch_bounds__(256, 2)
k2_pgen() {
    extern __shared__ float rt[];
    int tid = threadIdx.x;
    int b  = blockIdx.y;
    int a0 = blockIdx.x * 64;

    {
        const float* src = g_rightT + (size_t)b * NA * NR;
        for (int g = tid; g < NA * NR; g += 256)
            rt[g + g / 160] = src[g];
    }

    int mg = tid >> 4;     // 0..15
    int kg = tid & 15;     // 0..15

    float ls[4][NR];
#pragma unroll
    for (int i = 0; i < 4; i++) {
        const float* lp = g_left + ((size_t)b * NA + a0 + mg + 16 * i) * NR;
#pragma unroll
        for (int r = 0; r < NR; r++) ls[i][r] = lp[r];
    }
    float lacc[4] = {0.f, 0.f, 0.f, 0.f};

    __syncthreads();

    __half* pb = g_p + ((size_t)b * NA) * NA;

#pragma unroll 1
    for (int stripe = 0; stripe < 16; stripe++) {
        int cbase = stripe * 128 + kg * 8;
        float e[4][8];
#pragma unroll
        for (int j = 0; j < 8; j++) {
            int c = cbase + j;
            const float* rp = rt + c * NR + (c >> 4);
            float rv[NR];
#pragma unroll
            for (int r = 0; r < NR; r++) rv[r] = rp[r];
#pragma unroll
            for (int i = 0; i < 4; i++) {
                float s = 0.f;
#pragma unroll
                for (int r = 0; r < NR; r++) s += ls[i][r] * rv[r];
                float ev = __expf(s);
                e[i][j] = ev;
                lacc[i] += ev;
            }
        }
#pragma unroll
        for (int i = 0; i < 4; i++) {
            uint4 t;
            t.x = pack_h2(e[i][0], e[i][1]);
            t.y = pack_h2(e[i][2], e[i][3]);
            t.z = pack_h2(e[i][4], e[i][5]);
            t.w = pack_h2(e[i][6], e[i][7]);
            *(uint4*)(pb + (size_t)(a0 + mg + 16 * i) * NA + cbase) = t;
        }
    }

#pragma unroll
    for (int off = 1; off < 16; off <<= 1)
#pragma unroll
        for (int i = 0; i < 4; i++)
            lacc[i] += __shfl_xor_sync(0xffffffffu, lacc[i], off);
    if (kg == 0) {
#pragma unroll
        for (int i = 0; i < 4; i++)
            g_psum[(size_t)b * NA + a0 + mg + 16 * i] = lacc[i];
    }
}

// ===========================================================================
// K3: pure fp16 GEMM out = (P' @ xh) / psum.
//   CTA: M=128 x N=128, 256 threads (8 warps = 2m x 4n, warp tile 64x32),
//   2 CTAs/SM. KC=64 (4 k16 steps), 32 chunks.
//   Triple-buffered cp.async (A+B), prefetch distance 2 after the barrier,
//   wait_group 1 keeps one chunk in flight. One barrier per chunk.
// ===========================================================================
#define KC 64
#define NCHUNK (NA / KC)          // 32
#define AH_STRIDE 72              // halves
#define AH_BUF (128 * AH_STRIDE)  // 9216 halves per buffer
#define BH_STRIDE 136             // halves
#define BH_BUF (KC * BH_STRIDE)   // 8704 halves per buffer
// dynamic smem (bytes)
#define OFF_A 0                   // 3*9216*2 = 55296
#define OFF_B 55296               // 3*8704*2 = 52224
#define OFF_SL 107520             // 128*4 = 512
#define SMEM_K3 108032

__global__ void __launch_bounds__(256, 2)
k3_gemm(float* __restrict__ out) {
    extern __shared__ char smem[];
    float* sl = (float*)(smem + OFF_SL);
    uint32_t sb = smem_u32(smem);

    int tid = threadIdx.x;
    int wid = tid >> 5, lane = tid & 31;
    int b  = blockIdx.z;
    int a0 = blockIdx.x * 128;
    int n0 = blockIdx.y * 128;

    int wm = wid >> 2, wn = wid & 3;   // 2m x 4n, warp tile 64x32
    int fs = lane & 3, fq = lane >> 2;

    float acc[4][4][4];
#pragma unroll
    for (int mt = 0; mt < 4; mt++)
#pragma unroll
        for (int nt = 0; nt < 4; nt++)
#pragma unroll
            for (int q = 0; q < 4; q++) acc[mt][nt][q] = 0.f;

    const __half* pA = g_p  + ((size_t)b * NA + a0) * NA;   // rows stride NA
    const __half* pB = g_xh + (size_t)b * NA * ND;

#define PREFETCH(chunk, pb)                                                     \
    do {                                                                        \
        _Pragma("unroll")                                                       \
        for (int it = 0; it < 4; it++) {                                        \
            int u = tid + 256 * it;          /* 1024 units: A 128r x 8seg */    \
            int row = u >> 3, seg = u & 7;                                      \
            uint32_t dst = sb + OFF_A +                                         \
                (uint32_t)((pb) * AH_BUF + row * AH_STRIDE + seg * 8) * 2;      \
            cp_async16(dst, pA + (size_t)row * NA + (chunk) * KC + seg * 8);    \
        }                                                                       \
        _Pragma("unroll")                                                       \
        for (int it = 0; it < 4; it++) {                                        \
            int u = tid + 256 * it;          /* 1024 units: B 64r x 16seg */    \
            int row = u >> 4, seg = u & 15;                                     \
            uint32_t dst = sb + OFF_B +                                         \
                (uint32_t)((pb) * BH_BUF + row * BH_STRIDE + seg * 8) * 2;      \
            cp_async16(dst, pB + (size_t)((chunk) * KC + row) * ND + n0 + seg * 8); \
        }                                                                       \
    } while (0)

    // prologue: row sums + two chunks in flight
    if (tid < 128) sl[tid] = g_psum[(size_t)b * NA + a0 + tid];
    PREFETCH(0, 0); CP_COMMIT();
    PREFETCH(1, 1); CP_COMMIT();

    for (int c = 0; c < NCHUNK; c++) {
        int buf = c % 3;

        CP_WAIT1();        // chunk c landed (c+1 may be in flight)
        __syncthreads();   // visible to all; buffer (c+2)%3 free (MMA c-1 done)

        if (c + 2 < NCHUNK) PREFETCH(c + 2, (c + 2) % 3);
        CP_COMMIT();       // unconditional: keeps wait_group accounting fixed

        uint32_t abase = sb + OFF_A + (uint32_t)(buf * AH_BUF) * 2;
        uint32_t bbase = sb + OFF_B + (uint32_t)(buf * BH_BUF) * 2;
#pragma unroll
        for (int ks = 0; ks < 4; ks++) {
            uint32_t afr[4][4], bfr[4][2];
            {
                int arow = wm * 64 + (lane & 15);
                int acol = ks * 16 + (lane >> 4) * 8;
                uint32_t base = abase + (uint32_t)(arow * AH_STRIDE + acol) * 2;
#pragma unroll
                for (int mt = 0; mt < 4; mt++)
                    ldsm_x4(afr[mt], base + (uint32_t)(mt * 16 * AH_STRIDE) * 2);
            }
            {
                int brow = ks * 16 + (lane & 15);
                int bcol = wn * 32 + (lane >> 4) * 8;
                uint32_t base = bbase + (uint32_t)(brow * BH_STRIDE + bcol) * 2;
#pragma unroll
                for (int np = 0; np < 2; np++) {
                    uint32_t q[4];
                    ldsm_x4_t(q, base + (uint32_t)(np * 16) * 2);
                    bfr[2 * np][0]     = q[0]; bfr[2 * np][1]     = q[1];
                    bfr[2 * np + 1][0] = q[2]; bfr[2 * np + 1][1] = q[3];
                }
            }
#pragma unroll
            for (int mt = 0; mt < 4; mt++)
#pragma unroll
                for (int nt = 0; nt < 4; nt++)
                    mma_f16(acc[mt][nt], afr[mt], bfr[nt]);
        }
    }

    // epilogue: normalize + store
#pragma unroll
    for (int mt = 0; mt < 4; mt++) {
        int r0 = wm * 64 + mt * 16 + fq;
        int r1 = r0 + 8;
        float inv0 = 1.0f / sl[r0];
        float inv1 = 1.0f / sl[r1];
        float* op0 = out + ((size_t)b * NA + a0 + r0) * ND + n0;
        float* op1 = out + ((size_t)b * NA + a0 + r1) * ND + n0;
#pragma unroll
        for (int nt = 0; nt < 4; nt++) {
            int col = wn * 32 + nt * 8 + 2 * fs;
            float2 v0 = make_float2(acc[mt][nt][0] * inv0, acc[mt][nt][1] * inv0);
            float2 v1 = make_float2(acc[mt][nt][2] * inv1, acc[mt][nt][3] * inv1);
            *(float2*)&op0[col] = v0;
            *(float2*)&op1[col] = v1;
        }
    }
}

// ---------------------------------------------------------------------------
extern "C" void kernel_launch(void* const* d_in, const int* in_sizes, int n_in,
                              void* d_out, int out_size) {
    const float* x  = (const float*)d_in[0];
    const float* W1 = (const float*)d_in[1];
    const float* W2 = (const float*)d_in[2];
    float* out = (float*)d_out;

    static bool attr_set = false;
    if (!attr_set) {
        cudaFuncSetAttribute(k2_pgen, cudaFuncAttributeMaxDynamicSharedMemorySize, K2_SMEM);
        cudaFuncSetAttribute(k3_gemm, cudaFuncAttributeMaxDynamicSharedMemorySize, SMEM_K3);
        attr_set = true;
    }

    k1_proj<<<(NB * NA) / 32, 256>>>(x, W1, W2);
    k2_pgen<<<dim3(NA / 64, NB), 256, K2_SMEM>>>();
    k3_gemm<<<dim3(NA / 128, ND / 128, NB), 256, SMEM_K3>>>(out);
}

// round 13
// speedup vs baseline: 1.0661x; 1.0316x over previous
#include <cuda_runtime.h>
#include <cuda_fp16.h>
#include <cstdint>
#include <math.h>

#define NB 16
#define NA 2048
#define ND 512
#define NR 10
#define INV_SQRT_DK 0.04419417382415922f  // 1/sqrt(512)

// Scratch (no device allocations allowed)
__device__ float  g_left[(size_t)NB * NA * NR];    // left proj, pre-scaled by 1/sqrt(dk)
__device__ float  g_rightT[(size_t)NB * NA * NR];  // right proj, [b][c][r]
__device__ __half g_xh[(size_t)NB * NA * ND];      // x pre-converted to half
__device__ __half g_p[(size_t)NB * NA * NA];       // unnormalized attn weights exp(s), fp16
__device__ float  g_psum[(size_t)NB * NA];         // per-row softmax denominators

__device__ __forceinline__ uint32_t smem_u32(const void* p) {
    uint32_t a;
    asm("{ .reg .u64 t; cvta.to.shared.u64 t, %1; cvt.u32.u64 %0, t; }" : "=r"(a) : "l"(p));
    return a;
}
__device__ __forceinline__ void cp_async16(uint32_t saddr, const void* gptr) {
    asm volatile("cp.async.cg.shared.global [%0], [%1], 16;" :: "r"(saddr), "l"(gptr) : "memory");
}
#define CP_COMMIT() asm volatile("cp.async.commit_group;" ::: "memory")
#define CP_WAIT1()  asm volatile("cp.async.wait_group 1;" ::: "memory")

__device__ __forceinline__ void mma_f16(float* d, const uint32_t* a, const uint32_t* bfr) {
    asm volatile(
        "mma.sync.aligned.m16n8k16.row.col.f32.f16.f16.f32 "
        "{%0,%1,%2,%3}, {%4,%5,%6,%7}, {%8,%9}, {%0,%1,%2,%3};"
        : "+f"(d[0]), "+f"(d[1]), "+f"(d[2]), "+f"(d[3])
        : "r"(a[0]), "r"(a[1]), "r"(a[2]), "r"(a[3]), "r"(bfr[0]), "r"(bfr[1]));
}
__device__ __forceinline__ void ldsm_x4(uint32_t* r, uint32_t saddr) {
    asm volatile("ldmatrix.sync.aligned.m8n8.x4.shared.b16 {%0,%1,%2,%3}, [%4];"
                 : "=r"(r[0]), "=r"(r[1]), "=r"(r[2]), "=r"(r[3]) : "r"(saddr));
}
__device__ __forceinline__ void ldsm_x4_t(uint32_t* r, uint32_t saddr) {
    asm volatile("ldmatrix.sync.aligned.m8n8.x4.trans.shared.b16 {%0,%1,%2,%3}, [%4];"
                 : "=r"(r[0]), "=r"(r[1]), "=r"(r[2]), "=r"(r[3]) : "r"(saddr));
}
__device__ __forceinline__ uint32_t pack_h2(float lo, float hi) {
    uint32_t u;
    asm("cvt.rn.f16x2.f32 %0, %1, %2;" : "=r"(u) : "f"(hi), "f"(lo));  // lo -> .x
    return u;
}

// ===========================================================================
// K1: projections + x->half conversion. 4 rows/warp; float4 LDG/LDS/ST.
//   __launch_bounds__(256, 2): cap at 128 regs -> 2 CTAs/SM (was 211 -> 1).
// ===========================================================================
__global__ void __launch_bounds__(256, 2)
k1_proj(const float* __restrict__ x, const float* __restrict__ W1,
        const float* __restrict__ W2) {
    __shared__ float W1T[NR][ND];
    __shared__ float W2s[NR][ND];
    int tid = threadIdx.x;
    for (int idx = tid; idx < ND * NR; idx += 256) {
        int d = idx / NR, r = idx % NR;
        W1T[r][d] = W1[idx];               // W1 [D, R], r fastest
    }
    for (int idx = tid; idx < NR * ND; idx += 256) {
        W2s[idx / ND][idx % ND] = W2[idx]; // W2 [R, D], d fastest
    }
    __syncthreads();

    int warp = tid >> 5, lane = tid & 31;
    int row0 = blockIdx.x * 32 + warp * 4;
    const float4* xr4 = (const float4*)(x + (size_t)row0 * ND);  // row stride 128 f4
    __half* xh0 = g_xh + (size_t)row0 * ND;

    float accL[4][NR], accR[4][NR];
#pragma unroll
    for (int i = 0; i < 4; i++)
#pragma unroll
        for (int r = 0; r < NR; r++) { accL[i][r] = 0.f; accR[i][r] = 0.f; }

#pragma unroll
    for (int k = 0; k < 4; k++) {
        int q = lane + 32 * k;             // float4 index within row, 0..127
        float4 xv[4];
#pragma unroll
        for (int i = 0; i < 4; i++) xv[i] = xr4[(size_t)i * 128 + q];
#pragma unroll
        for (int i = 0; i < 4; i++) {
            uint2 h;
            h.x = pack_h2(xv[i].x, xv[i].y);
            h.y = pack_h2(xv[i].z, xv[i].w);
            *(uint2*)(xh0 + (size_t)i * ND + 4 * q) = h;
        }
#pragma unroll
        for (int r = 0; r < NR; r++) {
            float4 w1 = *(const float4*)&W1T[r][4 * q];
            float4 w2 = *(const float4*)&W2s[r][4 * q];
#pragma unroll
            for (int i = 0; i < 4; i++) {
                accL[i][r] += xv[i].x * w1.x + xv[i].y * w1.y
                            + xv[i].z * w1.z + xv[i].w * w1.w;
                accR[i][r] += xv[i].x * w2.x + xv[i].y * w2.y
                            + xv[i].z * w2.z + xv[i].w * w2.w;
            }
        }
    }
#pragma unroll
    for (int i = 0; i < 4; i++)
#pragma unroll
        for (int r = 0; r < NR; r++) {
#pragma unroll
            for (int off = 16; off; off >>= 1) {
                accL[i][r] += __shfl_down_sync(0xffffffffu, accL[i][r], off);
                accR[i][r] += __shfl_down_sync(0xffffffffu, accR[i][r], off);
            }
        }
    if (lane == 0) {
#pragma unroll
        for (int i = 0; i < 4; i++) {
            float* lp = g_left   + (size_t)(row0 + i) * NR;
            float* rp = g_rightT + (size_t)(row0 + i) * NR;
#pragma unroll
            for (int r = 0; r < NR; r++) {
                lp[r] = accL[i][r] * INV_SQRT_DK;
                rp[r] = accR[i][r];
            }
        }
    }
}

// ===========================================================================
// K2: P'[b][a][c] = exp(left_a . right_c) (fp16) + row sums (f32).
//   CTA: 64 rows x 2048 keys, 256 threads = 16 mg x 16 kg.
//   rightT staged once per batch block, swizzled for conflict-free LDS.
// ===========================================================================
#define K2_SMEM ((NA * NR + NA / 16 + 32) * 4)

__global__ void __launch_bounds__(256, 2)
k2_pgen() {
    extern __shared__ float rt[];
    int tid = threadIdx.x;
    int b  = blockIdx.y;
    int a0 = blockIdx.x * 64;

    {
        const float* src = g_rightT + (size_t)b * NA * NR;
        for (int g = tid; g < NA * NR; g += 256)
            rt[g + g / 160] = src[g];
    }

    int mg = tid >> 4;     // 0..15
    int kg = tid & 15;     // 0..15

    float ls[4][NR];
#pragma unroll
    for (int i = 0; i < 4; i++) {
        const float* lp = g_left + ((size_t)b * NA + a0 + mg + 16 * i) * NR;
#pragma unroll
        for (int r = 0; r < NR; r++) ls[i][r] = lp[r];
    }
    float lacc[4] = {0.f, 0.f, 0.f, 0.f};

    __syncthreads();

    __half* pb = g_p + ((size_t)b * NA) * NA;

#pragma unroll 1
    for (int stripe = 0; stripe < 16; stripe++) {
        int cbase = stripe * 128 + kg * 8;
        float e[4][8];
#pragma unroll
        for (int j = 0; j < 8; j++) {
            int c = cbase + j;
            const float* rp = rt + c * NR + (c >> 4);
            float rv[NR];
#pragma unroll
            for (int r = 0; r < NR; r++) rv[r] = rp[r];
#pragma unroll
            for (int i = 0; i < 4; i++) {
                float s = 0.f;
#pragma unroll
                for (int r = 0; r < NR; r++) s += ls[i][r] * rv[r];
                float ev = __expf(s);
                e[i][j] = ev;
                lacc[i] += ev;
            }
        }
#pragma unroll
        for (int i = 0; i < 4; i++) {
            uint4 t;
            t.x = pack_h2(e[i][0], e[i][1]);
            t.y = pack_h2(e[i][2], e[i][3]);
            t.z = pack_h2(e[i][4], e[i][5]);
            t.w = pack_h2(e[i][6], e[i][7]);
            *(uint4*)(pb + (size_t)(a0 + mg + 16 * i) * NA + cbase) = t;
        }
    }

#pragma unroll
    for (int off = 1; off < 16; off <<= 1)
#pragma unroll
        for (int i = 0; i < 4; i++)
            lacc[i] += __shfl_xor_sync(0xffffffffu, lacc[i], off);
    if (kg == 0) {
#pragma unroll
        for (int i = 0; i < 4; i++)
            g_psum[(size_t)b * NA + a0 + mg + 16 * i] = lacc[i];
    }
}

// ===========================================================================
// K3: pure fp16 GEMM out = (P' @ xh) / psum.
//   CTA: M=128 x N=128, 256 threads (8 warps = 2m x 4n, warp tile 64x32),
//   2 CTAs/SM. KC=64 (4 k16 steps), 32 chunks.
//   Triple-buffered cp.async (A+B), prefetch distance 2 after the barrier,
//   wait_group 1 keeps one chunk in flight. One barrier per chunk.
// ===========================================================================
#define KC 64
#define NCHUNK (NA / KC)          // 32
#define AH_STRIDE 72              // halves
#define AH_BUF (128 * AH_STRIDE)  // 9216 halves per buffer
#define BH_STRIDE 136             // halves
#define BH_BUF (KC * BH_STRIDE)   // 8704 halves per buffer
// dynamic smem (bytes)
#define OFF_A 0                   // 3*9216*2 = 55296
#define OFF_B 55296               // 3*8704*2 = 52224
#define OFF_SL 107520             // 128*4 = 512
#define SMEM_K3 108032

__global__ void __launch_bounds__(256, 2)
k3_gemm(float* __restrict__ out) {
    extern __shared__ char smem[];
    float* sl = (float*)(smem + OFF_SL);
    uint32_t sb = smem_u32(smem);

    int tid = threadIdx.x;
    int wid = tid >> 5, lane = tid & 31;
    int b  = blockIdx.z;
    int a0 = blockIdx.x * 128;
    int n0 = blockIdx.y * 128;

    int wm = wid >> 2, wn = wid & 3;   // 2m x 4n, warp tile 64x32
    int fs = lane & 3, fq = lane >> 2;

    float acc[4][4][4];
#pragma unroll
    for (int mt = 0; mt < 4; mt++)
#pragma unroll
        for (int nt = 0; nt < 4; nt++)
#pragma unroll
            for (int q = 0; q < 4; q++) acc[mt][nt][q] = 0.f;

    const __half* pA = g_p  + ((size_t)b * NA + a0) * NA;   // rows stride NA
    const __half* pB = g_xh + (size_t)b * NA * ND;

#define PREFETCH(chunk, pb)                                                     \
    do {                                                                        \
        _Pragma("unroll")                                                       \
        for (int it = 0; it < 4; it++) {                                        \
            int u = tid + 256 * it;          /* 1024 units: A 128r x 8seg */    \
            int row = u >> 3, seg = u & 7;                                      \
            uint32_t dst = sb + OFF_A +                                         \
                (uint32_t)((pb) * AH_BUF + row * AH_STRIDE + seg * 8) * 2;      \
            cp_async16(dst, pA + (size_t)row * NA + (chunk) * KC + seg * 8);    \
        }                                                                       \
        _Pragma("unroll")                                                       \
        for (int it = 0; it < 4; it++) {                                        \
            int u = tid + 256 * it;          /* 1024 units: B 64r x 16seg */    \
            int row = u >> 4, seg = u & 15;                                     \
            uint32_t dst = sb + OFF_B +                                         \
                (uint32_t)((pb) * BH_BUF + row * BH_STRIDE + seg * 8) * 2;      \
            cp_async16(dst, pB + (size_t)((chunk) * KC + row) * ND + n0 + seg * 8); \
        }                                                                       \
    } while (0)

    // prologue: row sums + two chunks in flight
    if (tid < 128) sl[tid] = g_psum[(size_t)b * NA + a0 + tid];
    PREFETCH(0, 0); CP_COMMIT();
    PREFETCH(1, 1); CP_COMMIT();

    for (int c = 0; c < NCHUNK; c++) {
        int buf = c % 3;

        CP_WAIT1();        // chunk c landed (c+1 may be in flight)
        __syncthreads();   // visible to all; buffer (c+2)%3 free (MMA c-1 done)

        if (c + 2 < NCHUNK) PREFETCH(c + 2, (c + 2) % 3);
        CP_COMMIT();       // unconditional: keeps wait_group accounting fixed

        uint32_t abase = sb + OFF_A + (uint32_t)(buf * AH_BUF) * 2;
        uint32_t bbase = sb + OFF_B + (uint32_t)(buf * BH_BUF) * 2;
#pragma unroll
        for (int ks = 0; ks < 4; ks++) {
            uint32_t afr[4][4], bfr[4][2];
            {
                int arow = wm * 64 + (lane & 15);
                int acol = ks * 16 + (lane >> 4) * 8;
                uint32_t base = abase + (uint32_t)(arow * AH_STRIDE + acol) * 2;
#pragma unroll
                for (int mt = 0; mt < 4; mt++)
                    ldsm_x4(afr[mt], base + (uint32_t)(mt * 16 * AH_STRIDE) * 2);
            }
            {
                int brow = ks * 16 + (lane & 15);
                int bcol = wn * 32 + (lane >> 4) * 8;
                uint32_t base = bbase + (uint32_t)(brow * BH_STRIDE + bcol) * 2;
#pragma unroll
                for (int np = 0; np < 2; np++) {
                    uint32_t q[4];
                    ldsm_x4_t(q, base + (uint32_t)(np * 16) * 2);
                    bfr[2 * np][0]     = q[0]; bfr[2 * np][1]     = q[1];
                    bfr[2 * np + 1][0] = q[2]; bfr[2 * np + 1][1] = q[3];
                }
            }
#pragma unroll
            for (int mt = 0; mt < 4; mt++)
#pragma unroll
                for (int nt = 0; nt < 4; nt++)
                    mma_f16(acc[mt][nt], afr[mt], bfr[nt]);
        }
    }

    // epilogue: normalize + store
#pragma unroll
    for (int mt = 0; mt < 4; mt++) {
        int r0 = wm * 64 + mt * 16 + fq;
        int r1 = r0 + 8;
        float inv0 = 1.0f / sl[r0];
        float inv1 = 1.0f / sl[r1];
        float* op0 = out + ((size_t)b * NA + a0 + r0) * ND + n0;
        float* op1 = out + ((size_t)b * NA + a0 + r1) * ND + n0;
#pragma unroll
        for (int nt = 0; nt < 4; nt++) {
            int col = wn * 32 + nt * 8 + 2 * fs;
            float2 v0 = make_float2(acc[mt][nt][0] * inv0, acc[mt][nt][1] * inv0);
            float2 v1 = make_float2(acc[mt][nt][2] * inv1, acc[mt][nt][3] * inv1);
            *(float2*)&op0[col] = v0;
            *(float2*)&op1[col] = v1;
        }
    }
}

// ---------------------------------------------------------------------------
extern "C" void kernel_launch(void* const* d_in, const int* in_sizes, int n_in,
                              void* d_out, int out_size) {
    const float* x  = (const float*)d_in[0];
    const float* W1 = (const float*)d_in[1];
    const float* W2 = (const float*)d_in[2];
    float* out = (float*)d_out;

    static bool attr_set = false;
    if (!attr_set) {
        cudaFuncSetAttribute(k2_pgen, cudaFuncAttributeMaxDynamicSharedMemorySize, K2_SMEM);
        cudaFuncSetAttribute(k3_gemm, cudaFuncAttributeMaxDynamicSharedMemorySize, SMEM_K3);
        attr_set = true;
    }

    k1_proj<<<(NB * NA) / 32, 256>>>(x, W1, W2);
    k2_pgen<<<dim3(NA / 64, NB), 256, K2_SMEM>>>();
    k3_gemm<<<dim3(NA / 128, ND / 128, NB), 256, SMEM_K3>>>(out);
}